// round 5
// baseline (speedup 1.0000x reference)
#include <cuda_runtime.h>
#include <cuda_bf16.h>
#include <cstdint>
#include <cstddef>

// Problem constants
#define NN     100000
#define NPAD   100096            // 782 * 128
#define NREL8  8
#define NRELT  16
#define DD     256
#define EE     262144            // 2^18
#define NTOT   (NRELT * DD)      // 4096   (N dim of Z)

// GEMM tiling
#define STAGE  65536
#define A_HI   0
#define A_LO   16384
#define B_HI   32768
#define B_LO   49152
#define SMEM_GEMM (2 * STAGE + 1024)

// ---------------- scratch (static device globals) --------------------------
__device__ __align__(16) float g_Z[(size_t)NPAD * NTOT];            // 1.64 GB
__device__ __align__(16) __nv_bfloat16 g_Xhi[(size_t)NPAD * DD];
__device__ __align__(16) __nv_bfloat16 g_Xlo[(size_t)NPAD * DD];
__device__ __align__(16) __nv_bfloat16 g_Whi[(size_t)NTOT * DD];    // B^T: [n][k]
__device__ __align__(16) __nv_bfloat16 g_Wlo[(size_t)NTOT * DD];
__device__ float g_deg[NRELT * NPAD];
__device__ float g_scale[NRELT * NPAD];      // invfull[r] * invdeg_i[r]
__device__ float g_invfull[NPAD];
__device__ unsigned g_indmask[NPAD];
__device__ __align__(16) float g_bW[NRELT * DD];

// ---------------- helpers ---------------------------------------------------
__device__ __forceinline__ void red_add_v4(float4* addr, float4 v) {
    asm volatile("red.global.add.v4.f32 [%0], {%1,%2,%3,%4};"
                 :: "l"(addr), "f"(v.x), "f"(v.y), "f"(v.z), "f"(v.w)
                 : "memory");
}
__device__ __forceinline__ uint32_t sw128(uint32_t o) { return o ^ ((o >> 3) & 0x70); }
__device__ __forceinline__ uint32_t pack_bf2(__nv_bfloat16 a, __nv_bfloat16 b) {
    return ((uint32_t)__bfloat16_as_ushort(b) << 16) | (uint32_t)__bfloat16_as_ushort(a);
}
__device__ __forceinline__ void cp16(uint32_t s, const void* g) {
    asm volatile("cp.async.cg.shared.global [%0], [%1], 16;"
                 :: "r"(s), "l"(__cvta_generic_to_global(g)) : "memory");
}
__device__ __forceinline__ void ldsm4(uint32_t r[4], uint32_t addr) {
    asm volatile("ldmatrix.sync.aligned.m8n8.x4.shared.b16 {%0,%1,%2,%3}, [%4];"
                 : "=r"(r[0]), "=r"(r[1]), "=r"(r[2]), "=r"(r[3]) : "r"(addr));
}
__device__ __forceinline__ void mma_bf16(float d[4], const uint32_t a[4],
                                         uint32_t b0, uint32_t b1) {
    asm volatile(
        "mma.sync.aligned.m16n8k16.row.col.f32.bf16.bf16.f32 "
        "{%0,%1,%2,%3}, {%4,%5,%6,%7}, {%8,%9}, {%0,%1,%2,%3};"
        : "+f"(d[0]), "+f"(d[1]), "+f"(d[2]), "+f"(d[3])
        : "r"(a[0]), "r"(a[1]), "r"(a[2]), "r"(a[3]), "r"(b0), "r"(b1));
}

// ---------------- small kernels ----------------------------------------------
__global__ void k_zdeg() {
    int i = blockIdx.x * blockDim.x + threadIdx.x;
    g_deg[i] = 0.f;
}

__global__ void k_deg(const int* __restrict__ adj_row,
                      const int* __restrict__ adj_t_row) {
    int idx = blockIdx.x * blockDim.x + threadIdx.x;
    int rel = idx >> 18;
    int e   = idx & (EE - 1);
    int r = (rel < NREL8) ? __ldg(&adj_row[rel * EE + e])
                          : __ldg(&adj_t_row[(rel - NREL8) * EE + e]);
    atomicAdd(&g_deg[rel * NPAD + r], 1.0f);
}

__global__ void k_norm() {
    int m = blockIdx.x * blockDim.x + threadIdx.x;
    if (m >= NPAD) return;
    float full = 0.f;
    unsigned mask = 0;
    float inv[NRELT];
    #pragma unroll
    for (int i = 0; i < NRELT; i++) {
        float d = g_deg[i * NPAD + m];
        if (d > 0.f) { full += 1.f; mask |= (1u << i); inv[i] = 1.f / d; }
        else inv[i] = 1.f;
    }
    float invf = (full > 0.f) ? (1.f / full) : 1.f;
    g_invfull[m] = invf;
    g_indmask[m] = mask;
    #pragma unroll
    for (int i = 0; i < NRELT; i++) g_scale[i * NPAD + m] = invf * inv[i];
}

__global__ void k_bw(const float* __restrict__ bias, const float* __restrict__ w,
                     const float* __restrict__ bias_t, const float* __restrict__ w_t) {
    int i = blockIdx.x;
    int n = threadIdx.x;
    const float* b = (i < NREL8) ? (bias + i * DD) : (bias_t + (i - NREL8) * DD);
    const float* W = (i < NREL8) ? (w + (size_t)i * DD * DD)
                                 : (w_t + (size_t)(i - NREL8) * DD * DD);
    float s = 0.f;
    for (int k = 0; k < DD; k++) s += b[k] * W[(size_t)k * DD + n];
    g_bW[i * DD + n] = s;
}

// Split W into bf16 hi/lo, B^T layout: g_Whi[(rel*256+c)*256 + k] = W_rel[k][c]
__global__ void k_prepW(const float* __restrict__ w, const float* __restrict__ w_t) {
    int idx = blockIdx.x * blockDim.x + threadIdx.x;   // NTOT*DD = 1048576
    int k   = idx & 255;
    int n   = idx >> 8;
    int rel = n >> 8;
    int c   = n & 255;
    const float* W = (rel < NREL8) ? (w + (size_t)rel * DD * DD)
                                   : (w_t + (size_t)(rel - NREL8) * DD * DD);
    float x = W[(size_t)k * DD + c];
    __nv_bfloat16 h = __float2bfloat16(x);
    g_Whi[idx] = h;
    g_Wlo[idx] = __float2bfloat16(x - __bfloat162float(h));
}

// Split X into bf16 hi/lo; pad rows -> 0
__global__ void k_prepX(const float* __restrict__ feat) {
    int idx = blockIdx.x * blockDim.x + threadIdx.x;   // NPAD*64
    int m = idx >> 6;
    float4 v = make_float4(0.f, 0.f, 0.f, 0.f);
    if (m < NN) v = reinterpret_cast<const float4*>(feat)[idx];
    __nv_bfloat16 h0 = __float2bfloat16(v.x), h1 = __float2bfloat16(v.y);
    __nv_bfloat16 h2 = __float2bfloat16(v.z), h3 = __float2bfloat16(v.w);
    uint2 hp, lp;
    hp.x = pack_bf2(h0, h1); hp.y = pack_bf2(h2, h3);
    lp.x = pack_bf2(__float2bfloat16(v.x - __bfloat162float(h0)),
                    __float2bfloat16(v.y - __bfloat162float(h1)));
    lp.y = pack_bf2(__float2bfloat16(v.z - __bfloat162float(h2)),
                    __float2bfloat16(v.w - __bfloat162float(h3)));
    reinterpret_cast<uint2*>(g_Xhi)[idx] = hp;
    reinterpret_cast<uint2*>(g_Xlo)[idx] = lp;
}

// out[m][:] = invfull[m] * sum_{i: deg_i[m]>0} bW_i[:]
__global__ void k_init(float* __restrict__ out) {
    __shared__ float4 bws[NRELT * 64];
    int tid = threadIdx.x;
    for (int x = tid; x < NRELT * 64; x += 256)
        bws[x] = reinterpret_cast<const float4*>(g_bW)[x];
    __syncthreads();
    int idx = blockIdx.x * 256 + tid;       // NN*64 exactly
    int m = idx >> 6, q = idx & 63;
    unsigned mask = g_indmask[m];
    float invf = g_invfull[m];
    float4 s = make_float4(0.f, 0.f, 0.f, 0.f);
    #pragma unroll
    for (int i = 0; i < NRELT; i++) {
        if ((mask >> i) & 1u) {
            float4 b = bws[i * 64 + q];
            s.x += b.x; s.y += b.y; s.z += b.z; s.w += b.w;
        }
    }
    s.x *= invf; s.y *= invf; s.z *= invf; s.w *= invf;
    reinterpret_cast<float4*>(out)[idx] = s;
}

// ---------------- GEMM: Z = X @ Wcat, 3-term bf16 split via mma.sync ---------
__device__ __forceinline__ void load_stage(uint32_t sb, int tid, int rowBase,
                                           int colBase, int kb) {
    #pragma unroll
    for (int p = 0; p < 4; p++) {
        int idx = tid + p * 256;
        int row = idx >> 3, ch = idx & 7;
        uint32_t so = sw128(row * 128 + ch * 16);
        size_t ga = (size_t)(rowBase + row) * DD + kb + ch * 8;
        size_t gb = (size_t)(colBase + row) * DD + kb + ch * 8;
        cp16(sb + A_HI + so, g_Xhi + ga);
        cp16(sb + A_LO + so, g_Xlo + ga);
        cp16(sb + B_HI + so, g_Whi + gb);
        cp16(sb + B_LO + so, g_Wlo + gb);
    }
    asm volatile("cp.async.commit_group;" ::: "memory");
}

__global__ void __launch_bounds__(256, 1) k_gemm() {
    extern __shared__ char smraw[];
    uint32_t sraw = (uint32_t)__cvta_generic_to_shared(smraw);
    uint32_t sbase = (sraw + 1023) & ~1023u;

    const int tid = threadIdx.x;
    const int lane = tid & 31;
    const int wid = tid >> 5;
    const int wm = wid >> 1;          // 0..3 (M dir, 32 rows each)
    const int wn = wid & 1;           // 0..1 (N dir, 64 cols each)
    const int rowBase = blockIdx.y * 128;
    const int colBase = blockIdx.x * 128;

    float acc[2][8][4] = {};

    uint32_t aoff[2], boff[4];
    #pragma unroll
    for (int mf = 0; mf < 2; mf++)
        aoff[mf] = sw128((wm * 32 + mf * 16 + (lane & 15)) * 128 + (lane >> 4) * 16);
    #pragma unroll
    for (int nf = 0; nf < 4; nf++)
        boff[nf] = sw128((wn * 64 + nf * 16 + (lane & 15)) * 128 + (lane >> 4) * 16);

    load_stage(sbase, tid, rowBase, colBase, 0);

    #pragma unroll
    for (int t = 0; t < 4; t++) {
        asm volatile("cp.async.wait_group 0;" ::: "memory");
        __syncthreads();
        if (t < 3) load_stage(sbase + ((t + 1) & 1) * STAGE, tid, rowBase, colBase, (t + 1) * 64);
        uint32_t sb = sbase + (t & 1) * STAGE;

        #pragma unroll
        for (int ks = 0; ks < 4; ks++) {
            // ks*32 hits the swizzle's XOR-target bits [5:6] -> compose with XOR.
            uint32_t kx = ks * 32;
            uint32_t ah[2][4], al[2][4], bh[4][4], bl[4][4];
            #pragma unroll
            for (int mf = 0; mf < 2; mf++) {
                uint32_t o = aoff[mf] ^ kx;
                ldsm4(ah[mf], sb + A_HI + o);
                ldsm4(al[mf], sb + A_LO + o);
            }
            #pragma unroll
            for (int nf = 0; nf < 4; nf++) {
                uint32_t o = boff[nf] ^ kx;
                ldsm4(bh[nf], sb + B_HI + o);
                ldsm4(bl[nf], sb + B_LO + o);
            }
            #pragma unroll
            for (int mf = 0; mf < 2; mf++) {
                #pragma unroll
                for (int j = 0; j < 8; j++) {
                    uint32_t b0h = bh[j >> 1][j & 1], b1h = bh[j >> 1][(j & 1) + 2];
                    uint32_t b0l = bl[j >> 1][j & 1], b1l = bl[j >> 1][(j & 1) + 2];
                    mma_bf16(acc[mf][j], ah[mf], b0h, b1h);   // hi*hi
                    mma_bf16(acc[mf][j], al[mf], b0h, b1h);   // lo*hi
                    mma_bf16(acc[mf][j], ah[mf], b0l, b1l);   // hi*lo
                }
            }
        }
    }

    // Epilogue: store Z
    float* Zb = g_Z + (size_t)(rowBase + wm * 32) * NTOT + colBase + wn * 64;
    #pragma unroll
    for (int mf = 0; mf < 2; mf++) {
        #pragma unroll
        for (int j = 0; j < 8; j++) {
            int r = mf * 16 + (lane >> 2);
            int cc = j * 8 + (lane & 3) * 2;
            float2 v0 = make_float2(acc[mf][j][0], acc[mf][j][1]);
            float2 v1 = make_float2(acc[mf][j][2], acc[mf][j][3]);
            *reinterpret_cast<float2*>(Zb + (size_t)r * NTOT + cc) = v0;
            *reinterpret_cast<float2*>(Zb + (size_t)(r + 8) * NTOT + cc) = v1;
        }
    }
}

// ---------------- scatter, two column-half passes -----------------------------
// gw decode: half = gw >> 22, rel = (gw >> 18) & 15, e = gw & (EE-1).
// CTAs launch in blockIdx order, so within a half-pass the 16 relations run
// ~sequentially: L2 working set = Z half-slice (51 MB) + out half (51 MB),
// and the out half stays L2-resident across the whole pass.
__global__ void k_scatter2(const int* __restrict__ adj_row, const int* __restrict__ adj_col,
                           const int* __restrict__ adj_t_row, const int* __restrict__ adj_t_col,
                           float* __restrict__ out) {
    unsigned gw = ((unsigned)blockIdx.x * blockDim.x + threadIdx.x) >> 5;
    int lane = threadIdx.x & 31;
    int e    = gw & (EE - 1);
    int rel  = (gw >> 18) & 15;
    int half = gw >> 22;
    int r, c;
    if (rel < NREL8) {
        r = __ldg(&adj_row[rel * EE + e]);
        c = __ldg(&adj_col[rel * EE + e]);
    } else {
        int rr = rel - NREL8;
        r = __ldg(&adj_t_row[rr * EE + e]);
        c = __ldg(&adj_t_col[rr * EE + e]);
    }
    float s = g_scale[rel * NPAD + r];
    const float4* src = reinterpret_cast<const float4*>(
        g_Z + (size_t)c * NTOT + rel * DD + half * 128);
    float4* dst = reinterpret_cast<float4*>(out + (size_t)r * DD + half * 128);
    float4 v = __ldg(&src[lane]);
    v.x *= s; v.y *= s; v.z *= s; v.w *= s;
    red_add_v4(dst + lane, v);
}

// ---------------- launch ------------------------------------------------------
extern "C" void kernel_launch(void* const* d_in, const int* in_sizes, int n_in,
                              void* d_out, int out_size) {
    const float* features  = (const float*)d_in[0];
    const float* w         = (const float*)d_in[1];
    const float* bias      = (const float*)d_in[2];
    const float* w_t       = (const float*)d_in[3];
    const float* bias_t    = (const float*)d_in[4];
    const int*   adj_row   = (const int*)d_in[5];
    const int*   adj_col   = (const int*)d_in[6];
    const int*   adj_t_row = (const int*)d_in[7];
    const int*   adj_t_col = (const int*)d_in[8];
    float* out = (float*)d_out;

    cudaFuncSetAttribute(k_gemm, cudaFuncAttributeMaxDynamicSharedMemorySize, SMEM_GEMM);

    k_zdeg<<<(NRELT * NPAD) / 256, 256>>>();
    k_deg<<<(NRELT * EE) / 256, 256>>>(adj_row, adj_t_row);
    k_norm<<<(NPAD + 255) / 256, 256>>>();
    k_bw<<<NRELT, 256>>>(bias, w, bias_t, w_t);
    k_prepW<<<(NTOT * DD) / 256, 256>>>(w, w_t);
    k_prepX<<<(NPAD * 64) / 256, 256>>>(features);
    k_init<<<(NN * 64) / 256, 256>>>(out);
    k_gemm<<<dim3(NTOT / 128, NPAD / 128), 256, SMEM_GEMM>>>();
    // 2 halves * 16 rels * EE edges, one warp per (edge, half)
    k_scatter2<<<(2u * NRELT * EE) / 8, 256>>>(adj_row, adj_col, adj_t_row, adj_t_col, out);
}

// round 6
// speedup vs baseline: 1.1807x; 1.1807x over previous
#include <cuda_runtime.h>
#include <cuda_bf16.h>
#include <cstdint>
#include <cstddef>

// Problem constants
#define NN     100000
#define NPAD   100096            // 782 * 128
#define NREL8  8
#define NRELT  16
#define DD     256
#define EE     262144            // 2^18
#define NTOT   (NRELT * DD)      // 4096
#define NB     (NRELT * NPAD)    // 1601536 bins
#define NBLK   (NB / 256)        // 6256

// GEMM tiling
#define STAGE  65536
#define A_HI   0
#define A_LO   16384
#define B_HI   32768
#define B_LO   49152
#define SMEM_GEMM (2 * STAGE + 1024)

// ---------------- scratch (static device globals) --------------------------
__device__ __align__(16) float g_Z[(size_t)NPAD * NTOT];            // 1.64 GB
__device__ __align__(16) __nv_bfloat16 g_Xhi[(size_t)NPAD * DD];
__device__ __align__(16) __nv_bfloat16 g_Xlo[(size_t)NPAD * DD];
__device__ __align__(16) __nv_bfloat16 g_Whi[(size_t)NTOT * DD];    // B^T: [n][k]
__device__ __align__(16) __nv_bfloat16 g_Wlo[(size_t)NTOT * DD];
__device__ int   g_degi[NB];
__device__ int   g_roff[NB];
__device__ int   g_cur[NB];
__device__ int   g_bsum[NBLK];
__device__ int   g_ecol[NRELT * EE];
__device__ float g_scale[NB];                // invfull[r] * invdeg_i[r]
__device__ float g_invfull[NPAD];
__device__ unsigned g_indmask[NPAD];
__device__ __align__(16) float g_bW[NRELT * DD];

// ---------------- helpers ---------------------------------------------------
__device__ __forceinline__ uint32_t sw128(uint32_t o) { return o ^ ((o >> 3) & 0x70); }
__device__ __forceinline__ uint32_t pack_bf2(__nv_bfloat16 a, __nv_bfloat16 b) {
    return ((uint32_t)__bfloat16_as_ushort(b) << 16) | (uint32_t)__bfloat16_as_ushort(a);
}
__device__ __forceinline__ void cp16(uint32_t s, const void* g) {
    asm volatile("cp.async.cg.shared.global [%0], [%1], 16;"
                 :: "r"(s), "l"(__cvta_generic_to_global(g)) : "memory");
}
__device__ __forceinline__ void ldsm4(uint32_t r[4], uint32_t addr) {
    asm volatile("ldmatrix.sync.aligned.m8n8.x4.shared.b16 {%0,%1,%2,%3}, [%4];"
                 : "=r"(r[0]), "=r"(r[1]), "=r"(r[2]), "=r"(r[3]) : "r"(addr));
}
__device__ __forceinline__ void mma_bf16(float d[4], const uint32_t a[4],
                                         uint32_t b0, uint32_t b1) {
    asm volatile(
        "mma.sync.aligned.m16n8k16.row.col.f32.bf16.bf16.f32 "
        "{%0,%1,%2,%3}, {%4,%5,%6,%7}, {%8,%9}, {%0,%1,%2,%3};"
        : "+f"(d[0]), "+f"(d[1]), "+f"(d[2]), "+f"(d[3])
        : "r"(a[0]), "r"(a[1]), "r"(a[2]), "r"(a[3]), "r"(b0), "r"(b1));
}
__device__ __forceinline__ void edge_rc(int rel, int e,
                                        const int* adj_row, const int* adj_col,
                                        const int* adj_t_row, const int* adj_t_col,
                                        int& r, int& c) {
    if (rel < NREL8) {
        r = __ldg(&adj_row[rel * EE + e]);
        c = __ldg(&adj_col[rel * EE + e]);
    } else {
        int rr = rel - NREL8;
        r = __ldg(&adj_t_row[rr * EE + e]);
        c = __ldg(&adj_t_col[rr * EE + e]);
    }
}

// ---------------- CSR build --------------------------------------------------
__global__ void k_zdeg() {
    g_degi[blockIdx.x * blockDim.x + threadIdx.x] = 0;
}

__global__ void k_deg(const int* __restrict__ adj_row,
                      const int* __restrict__ adj_t_row) {
    int idx = blockIdx.x * blockDim.x + threadIdx.x;
    int rel = idx >> 18;
    int e   = idx & (EE - 1);
    int r = (rel < NREL8) ? __ldg(&adj_row[rel * EE + e])
                          : __ldg(&adj_t_row[(rel - NREL8) * EE + e]);
    atomicAdd(&g_degi[rel * NPAD + r], 1);
}

__global__ void k_scanA() {
    __shared__ int sh[256];
    int b = blockIdx.x, t = threadIdx.x;
    int v = g_degi[b * 256 + t];
    sh[t] = v; __syncthreads();
    #pragma unroll
    for (int o = 1; o < 256; o <<= 1) {
        int x = (t >= o) ? sh[t - o] : 0;
        __syncthreads();
        sh[t] += x;
        __syncthreads();
    }
    g_roff[b * 256 + t] = sh[t] - v;     // exclusive within block
    if (t == 255) g_bsum[b] = sh[255];
}

__global__ void k_scanB() {
    __shared__ int sh[256];
    __shared__ int run;
    int t = threadIdx.x;
    if (t == 0) run = 0;
    __syncthreads();
    for (int base = 0; base < NBLK; base += 256) {
        int idx = base + t;
        int v = (idx < NBLK) ? g_bsum[idx] : 0;
        sh[t] = v; __syncthreads();
        #pragma unroll
        for (int o = 1; o < 256; o <<= 1) {
            int x = (t >= o) ? sh[t - o] : 0;
            __syncthreads();
            sh[t] += x;
            __syncthreads();
        }
        if (idx < NBLK) g_bsum[idx] = run + sh[t] - v;   // exclusive block offsets
        __syncthreads();
        if (t == 255) run += sh[255];
        __syncthreads();
    }
}

__global__ void k_scanC() {
    int i = blockIdx.x * 256 + threadIdx.x;
    int v = g_roff[i] + g_bsum[i >> 8];
    g_roff[i] = v;
    g_cur[i]  = v;
}

__global__ void k_ecol(const int* __restrict__ adj_row, const int* __restrict__ adj_col,
                       const int* __restrict__ adj_t_row, const int* __restrict__ adj_t_col) {
    int idx = blockIdx.x * blockDim.x + threadIdx.x;
    int rel = idx >> 18;
    int e   = idx & (EE - 1);
    int r, c;
    edge_rc(rel, e, adj_row, adj_col, adj_t_row, adj_t_col, r, c);
    int pos = atomicAdd(&g_cur[rel * NPAD + r], 1);
    g_ecol[pos] = c;
}

// ---------------- norms / bias ------------------------------------------------
__global__ void k_norm() {
    int m = blockIdx.x * blockDim.x + threadIdx.x;
    if (m >= NPAD) return;
    float full = 0.f;
    unsigned mask = 0;
    float inv[NRELT];
    #pragma unroll
    for (int i = 0; i < NRELT; i++) {
        int d = g_degi[i * NPAD + m];
        if (d > 0) { full += 1.f; mask |= (1u << i); inv[i] = 1.f / (float)d; }
        else inv[i] = 1.f;
    }
    float invf = (full > 0.f) ? (1.f / full) : 1.f;
    g_invfull[m] = invf;
    g_indmask[m] = mask;
    #pragma unroll
    for (int i = 0; i < NRELT; i++) g_scale[i * NPAD + m] = invf * inv[i];
}

__global__ void k_bw(const float* __restrict__ bias, const float* __restrict__ w,
                     const float* __restrict__ bias_t, const float* __restrict__ w_t) {
    int i = blockIdx.x;
    int n = threadIdx.x;
    const float* b = (i < NREL8) ? (bias + i * DD) : (bias_t + (i - NREL8) * DD);
    const float* W = (i < NREL8) ? (w + (size_t)i * DD * DD)
                                 : (w_t + (size_t)(i - NREL8) * DD * DD);
    float s = 0.f;
    for (int k = 0; k < DD; k++) s += b[k] * W[(size_t)k * DD + n];
    g_bW[i * DD + n] = s;
}

// Split W into bf16 hi/lo, B^T layout: g_Whi[(rel*256+c)*256 + k] = W_rel[k][c]
__global__ void k_prepW(const float* __restrict__ w, const float* __restrict__ w_t) {
    int idx = blockIdx.x * blockDim.x + threadIdx.x;
    int k   = idx & 255;
    int n   = idx >> 8;
    int rel = n >> 8;
    int c   = n & 255;
    const float* W = (rel < NREL8) ? (w + (size_t)rel * DD * DD)
                                   : (w_t + (size_t)(rel - NREL8) * DD * DD);
    float x = W[(size_t)k * DD + c];
    __nv_bfloat16 h = __float2bfloat16(x);
    g_Whi[idx] = h;
    g_Wlo[idx] = __float2bfloat16(x - __bfloat162float(h));
}

// Split X into bf16 hi/lo; pad rows -> 0
__global__ void k_prepX(const float* __restrict__ feat) {
    int idx = blockIdx.x * blockDim.x + threadIdx.x;   // NPAD*64
    int m = idx >> 6;
    float4 v = make_float4(0.f, 0.f, 0.f, 0.f);
    if (m < NN) v = reinterpret_cast<const float4*>(feat)[idx];
    __nv_bfloat16 h0 = __float2bfloat16(v.x), h1 = __float2bfloat16(v.y);
    __nv_bfloat16 h2 = __float2bfloat16(v.z), h3 = __float2bfloat16(v.w);
    uint2 hp, lp;
    hp.x = pack_bf2(h0, h1); hp.y = pack_bf2(h2, h3);
    lp.x = pack_bf2(__float2bfloat16(v.x - __bfloat162float(h0)),
                    __float2bfloat16(v.y - __bfloat162float(h1)));
    lp.y = pack_bf2(__float2bfloat16(v.z - __bfloat162float(h2)),
                    __float2bfloat16(v.w - __bfloat162float(h3)));
    reinterpret_cast<uint2*>(g_Xhi)[idx] = hp;
    reinterpret_cast<uint2*>(g_Xlo)[idx] = lp;
}

// out[m][:] = invfull[m] * sum_{i: deg_i[m]>0} bW_i[:]
__global__ void k_init(float* __restrict__ out) {
    __shared__ float4 bws[NRELT * 64];
    int tid = threadIdx.x;
    for (int x = tid; x < NRELT * 64; x += 256)
        bws[x] = reinterpret_cast<const float4*>(g_bW)[x];
    __syncthreads();
    int idx = blockIdx.x * 256 + tid;       // NN*64 exactly
    int m = idx >> 6, q = idx & 63;
    unsigned mask = g_indmask[m];
    float invf = g_invfull[m];
    float4 s = make_float4(0.f, 0.f, 0.f, 0.f);
    #pragma unroll
    for (int i = 0; i < NRELT; i++) {
        if ((mask >> i) & 1u) {
            float4 b = bws[i * 64 + q];
            s.x += b.x; s.y += b.y; s.z += b.z; s.w += b.w;
        }
    }
    s.x *= invf; s.y *= invf; s.z *= invf; s.w *= invf;
    reinterpret_cast<float4*>(out)[idx] = s;
}

// ---------------- GEMM: Z = X @ Wcat, 3-term bf16 split via mma.sync ---------
__device__ __forceinline__ void load_stage(uint32_t sb, int tid, int rowBase,
                                           int colBase, int kb) {
    #pragma unroll
    for (int p = 0; p < 4; p++) {
        int idx = tid + p * 256;
        int row = idx >> 3, ch = idx & 7;
        uint32_t so = sw128(row * 128 + ch * 16);
        size_t ga = (size_t)(rowBase + row) * DD + kb + ch * 8;
        size_t gb = (size_t)(colBase + row) * DD + kb + ch * 8;
        cp16(sb + A_HI + so, g_Xhi + ga);
        cp16(sb + A_LO + so, g_Xlo + ga);
        cp16(sb + B_HI + so, g_Whi + gb);
        cp16(sb + B_LO + so, g_Wlo + gb);
    }
    asm volatile("cp.async.commit_group;" ::: "memory");
}

__global__ void __launch_bounds__(256, 1) k_gemm() {
    extern __shared__ char smraw[];
    uint32_t sraw = (uint32_t)__cvta_generic_to_shared(smraw);
    uint32_t sbase = (sraw + 1023) & ~1023u;

    const int tid = threadIdx.x;
    const int lane = tid & 31;
    const int wid = tid >> 5;
    const int wm = wid >> 1;
    const int wn = wid & 1;
    const int rowBase = blockIdx.y * 128;
    const int colBase = blockIdx.x * 128;

    float acc[2][8][4] = {};

    uint32_t aoff[2], boff[4];
    #pragma unroll
    for (int mf = 0; mf < 2; mf++)
        aoff[mf] = sw128((wm * 32 + mf * 16 + (lane & 15)) * 128 + (lane >> 4) * 16);
    #pragma unroll
    for (int nf = 0; nf < 4; nf++)
        boff[nf] = sw128((wn * 64 + nf * 16 + (lane & 15)) * 128 + (lane >> 4) * 16);

    load_stage(sbase, tid, rowBase, colBase, 0);

    #pragma unroll
    for (int t = 0; t < 4; t++) {
        asm volatile("cp.async.wait_group 0;" ::: "memory");
        __syncthreads();
        if (t < 3) load_stage(sbase + ((t + 1) & 1) * STAGE, tid, rowBase, colBase, (t + 1) * 64);
        uint32_t sb = sbase + (t & 1) * STAGE;

        #pragma unroll
        for (int ks = 0; ks < 4; ks++) {
            // ks*32 hits the swizzle's XOR-target bits [5:6] -> compose with XOR.
            uint32_t kx = ks * 32;
            uint32_t ah[2][4], al[2][4], bh[4][4], bl[4][4];
            #pragma unroll
            for (int mf = 0; mf < 2; mf++) {
                uint32_t o = aoff[mf] ^ kx;
                ldsm4(ah[mf], sb + A_HI + o);
                ldsm4(al[mf], sb + A_LO + o);
            }
            #pragma unroll
            for (int nf = 0; nf < 4; nf++) {
                uint32_t o = boff[nf] ^ kx;
                ldsm4(bh[nf], sb + B_HI + o);
                ldsm4(bl[nf], sb + B_LO + o);
            }
            #pragma unroll
            for (int mf = 0; mf < 2; mf++) {
                #pragma unroll
                for (int j = 0; j < 8; j++) {
                    uint32_t b0h = bh[j >> 1][j & 1], b1h = bh[j >> 1][(j & 1) + 2];
                    uint32_t b0l = bl[j >> 1][j & 1], b1l = bl[j >> 1][(j & 1) + 2];
                    mma_bf16(acc[mf][j], ah[mf], b0h, b1h);   // hi*hi
                    mma_bf16(acc[mf][j], al[mf], b0h, b1h);   // lo*hi
                    mma_bf16(acc[mf][j], ah[mf], b0l, b1l);   // hi*lo
                }
            }
        }
    }

    float* Zb = g_Z + (size_t)(rowBase + wm * 32) * NTOT + colBase + wn * 64;
    #pragma unroll
    for (int mf = 0; mf < 2; mf++) {
        #pragma unroll
        for (int j = 0; j < 8; j++) {
            int r = mf * 16 + (lane >> 2);
            int cc = j * 8 + (lane & 3) * 2;
            float2 v0 = make_float2(acc[mf][j][0], acc[mf][j][1]);
            float2 v1 = make_float2(acc[mf][j][2], acc[mf][j][3]);
            *reinterpret_cast<float2*>(Zb + (size_t)r * NTOT + cc) = v0;
            *reinterpret_cast<float2*>(Zb + (size_t)(r + 8) * NTOT + cc) = v1;
        }
    }
}

// ---------------- CSR gather: one warp owns one output row (no atomics) -------
__global__ void __launch_bounds__(256) k_gather(float* __restrict__ out) {
    unsigned gw = ((unsigned)blockIdx.x * blockDim.x + threadIdx.x) >> 5;
    int lane = threadIdx.x & 31;
    if (gw >= NN) return;
    int row = (int)gw;

    float4* outv = reinterpret_cast<float4*>(out);
    float4 a0 = outv[(size_t)row * 64 + lane];        // bias base from k_init
    float4 a1 = outv[(size_t)row * 64 + lane + 32];

    #pragma unroll 1
    for (int rel = 0; rel < NRELT; rel++) {
        int bin = rel * NPAD + row;
        int d = g_degi[bin];
        if (d == 0) continue;
        int s0 = g_roff[bin];
        float s = g_scale[bin];
        const float* zb = g_Z + rel * DD;
        #pragma unroll 2
        for (int j = 0; j < d; j++) {
            int c = __ldg(&g_ecol[s0 + j]);
            const float4* zp = reinterpret_cast<const float4*>(zb + (size_t)c * NTOT);
            float4 v0 = __ldg(zp + lane);
            float4 v1 = __ldg(zp + lane + 32);
            a0.x += s * v0.x; a0.y += s * v0.y; a0.z += s * v0.z; a0.w += s * v0.w;
            a1.x += s * v1.x; a1.y += s * v1.y; a1.z += s * v1.z; a1.w += s * v1.w;
        }
    }
    outv[(size_t)row * 64 + lane] = a0;
    outv[(size_t)row * 64 + lane + 32] = a1;
}

// ---------------- launch ------------------------------------------------------
extern "C" void kernel_launch(void* const* d_in, const int* in_sizes, int n_in,
                              void* d_out, int out_size) {
    const float* features  = (const float*)d_in[0];
    const float* w         = (const float*)d_in[1];
    const float* bias      = (const float*)d_in[2];
    const float* w_t       = (const float*)d_in[3];
    const float* bias_t    = (const float*)d_in[4];
    const int*   adj_row   = (const int*)d_in[5];
    const int*   adj_col   = (const int*)d_in[6];
    const int*   adj_t_row = (const int*)d_in[7];
    const int*   adj_t_col = (const int*)d_in[8];
    float* out = (float*)d_out;

    cudaFuncSetAttribute(k_gemm, cudaFuncAttributeMaxDynamicSharedMemorySize, SMEM_GEMM);

    k_zdeg<<<NB / 256, 256>>>();
    k_deg<<<(NRELT * EE) / 256, 256>>>(adj_row, adj_t_row);
    k_scanA<<<NBLK, 256>>>();
    k_scanB<<<1, 256>>>();
    k_scanC<<<NBLK, 256>>>();
    k_ecol<<<(NRELT * EE) / 256, 256>>>(adj_row, adj_col, adj_t_row, adj_t_col);
    k_norm<<<(NPAD + 255) / 256, 256>>>();
    k_bw<<<NRELT, 256>>>(bias, w, bias_t, w_t);
    k_prepW<<<(NTOT * DD) / 256, 256>>>(w, w_t);
    k_prepX<<<(NPAD * 64) / 256, 256>>>(features);
    k_init<<<(NN * 64) / 256, 256>>>(out);
    k_gemm<<<dim3(NTOT / 128, NPAD / 128), 256, SMEM_GEMM>>>();
    k_gather<<<(NN * 32) / 256, 256>>>(out);
}